// round 1
// baseline (speedup 1.0000x reference)
#include <cuda_runtime.h>

#define B_    16
#define C_    64
#define WH    65536                 // 256*256
#define NPIX  (B_ * WH)             // 1,048,576 pixels
#define NELEM (B_ * C_ * WH)        // 67,108,864 elements
#define EPS_  0.001f

// ---- scratch (device globals; no allocations allowed) ----
__device__ unsigned int g_mask[NPIX / 32];   // 1 bit per (b,w,h) pixel, 128 KB
__device__ int          g_n[B_];             // masked count per batch
__device__ float        g_S[C_];             // per-channel sum of masked x
__device__ float        g_Q[C_];             // per-channel sum of masked x^2
__device__ float        g_inv[C_];           // 1/sqrt(var+eps)
__device__ int          g_f[B_];             // pad_b > 0 flag

// ---- reset accumulators (graph replays must be deterministic) ----
__global__ void k_init() {
    int t = threadIdx.x;
    if (t < C_) { g_S[t] = 0.0f; g_Q[t] = 0.0f; }
    if (t < B_) g_n[t] = 0;
}

// ---- mask pass: m = (x[b,0,p]!=0 || x[b,1,p]!=0); build bitmask + counts ----
// 8 MB read total. Each thread covers 4 consecutive pixels (one nibble).
__global__ void __launch_bounds__(256) k_mask(const float* __restrict__ x) {
    int gid = blockIdx.x * 256 + threadIdx.x;      // 0 .. NPIX/4-1
    int pix = gid << 2;                            // global pixel index
    int b   = pix >> 16;
    int p   = pix & (WH - 1);
    float4 a = __ldg((const float4*)(x + (size_t)(b * C_    ) * WH + p));
    float4 c = __ldg((const float4*)(x + (size_t)(b * C_ + 1) * WH + p));
    unsigned nib = (((a.x != 0.0f) | (c.x != 0.0f)) ? 1u : 0u)
                 | (((a.y != 0.0f) | (c.y != 0.0f)) ? 2u : 0u)
                 | (((a.z != 0.0f) | (c.z != 0.0f)) ? 4u : 0u)
                 | (((a.w != 0.0f) | (c.w != 0.0f)) ? 8u : 0u);
    unsigned lane = threadIdx.x & 31u;
    // 8-lane groups assemble one 32-bit mask word (bit j <-> pixel wordbase+j)
    unsigned grpmask = 0xFFu << (lane & 24u);
    unsigned word = __reduce_or_sync(grpmask, nib << ((lane & 7u) * 4u));
    if ((lane & 7u) == 0u) g_mask[pix >> 5] = word;
    // per-batch masked-pixel count (warp never straddles a batch: 65536%128==0)
    int cnt  = __popc(nib);
    int wsum = __reduce_add_sync(0xFFFFFFFFu, cnt);
    if (lane == 0) atomicAdd(&g_n[b], wsum);
}

// ---- stats pass: per-channel S = sum m*x, Q = sum m*x^2 (256 MB read) ----
// One block per (plane, chunk): plane = b*64+c, 4 chunks of 16384 floats.
__global__ void __launch_bounds__(256) k_stats(const float* __restrict__ x) {
    int blk   = blockIdx.x;          // 0..4095
    int plane = blk >> 2;            // b*64 + c
    int chunk = blk & 3;
    int c = plane & (C_ - 1);
    int b = plane >> 6;
    const float4*       base  = (const float4*)(x + (size_t)plane * WH + chunk * 16384);
    const unsigned int* mbase = g_mask + (b << 11);
    int pbase = chunk * 16384;

    float s0 = 0.0f, s1 = 0.0f, q0 = 0.0f, q1 = 0.0f;
    #pragma unroll
    for (int k = 0; k < 16; k++) {
        int idx4 = k * 256 + threadIdx.x;
        float4 v = __ldg(base + idx4);
        int p = pbase + (idx4 << 2);
        unsigned mw   = __ldg(mbase + (p >> 5));     // L1/L2 hit (shared by 8 threads)
        unsigned bits = (mw >> (p & 31)) & 0xFu;
        if (bits & 1u) { s0 += v.x; q0 = fmaf(v.x, v.x, q0); }
        if (bits & 2u) { s1 += v.y; q1 = fmaf(v.y, v.y, q1); }
        if (bits & 4u) { s0 += v.z; q0 = fmaf(v.z, v.z, q0); }
        if (bits & 8u) { s1 += v.w; q1 = fmaf(v.w, v.w, q1); }
    }
    float s = s0 + s1, q = q0 + q1;
    #pragma unroll
    for (int o = 16; o; o >>= 1) {
        s += __shfl_xor_sync(0xFFFFFFFFu, s, o);
        q += __shfl_xor_sync(0xFFFFFFFFu, q, o);
    }
    __shared__ float ss[8], sq[8];
    int w = threadIdx.x >> 5;
    if ((threadIdx.x & 31) == 0) { ss[w] = s; sq[w] = q; }
    __syncthreads();
    if (threadIdx.x == 0) {
        float S = 0.0f, Q = 0.0f;
        #pragma unroll
        for (int i = 0; i < 8; i++) { S += ss[i]; Q += sq[i]; }
        atomicAdd(&g_S[c], S);   // 64 atomics per channel total
        atomicAdd(&g_Q[c], Q);
    }
}

// ---- finalize: add pad*x00 terms, compute inv[c] and pad flags ----
__global__ void k_finalize(const float* __restrict__ x) {
    int c = threadIdx.x;             // 0..63
    int nb[B_];
    int nmax = 0;
    #pragma unroll
    for (int b = 0; b < B_; b++) { nb[b] = g_n[b]; nmax = max(nmax, nb[b]); }
    float S = g_S[c], Q = g_Q[c];
    #pragma unroll
    for (int b = 0; b < B_; b++) {
        float pad = (float)(nmax - nb[b]);
        float x00 = x[(size_t)(b * C_ + c) << 16];
        S = fmaf(pad, x00, S);
        Q = fmaf(pad * x00, x00, Q);
    }
    float total = (float)(B_ * nmax);
    float mean  = S / total;
    float var   = Q / total - mean * mean;   // == weighted E[(x-mean)^2]
    g_inv[c] = rsqrtf(var + EPS_);
    if (c < B_) g_f[c] = (nmax - nb[c]) > 0 ? 1 : 0;
}

// ---- normalize: out = m ? x*inv : x, with (0,0) pad override (512 MB) ----
__global__ void __launch_bounds__(256) k_norm(const float* __restrict__ x,
                                              float* __restrict__ out) {
    int gid = blockIdx.x * 256 + threadIdx.x;   // float4 index
    int e = gid << 2;
    int plane = e >> 16;
    int p = e & (WH - 1);
    int c = plane & (C_ - 1);
    int b = plane >> 6;
    float inv = __ldg(&g_inv[c]);
    unsigned mw   = __ldg(&g_mask[(b << 11) + (p >> 5)]);
    unsigned bits = (mw >> (p & 31)) & 0xFu;
    if (p == 0) bits |= (unsigned)g_f[b];       // force-normalize (0,0) if pad>0
    float4 v = __ldg((const float4*)x + gid);
    float4 o;
    o.x = (bits & 1u) ? v.x * inv : v.x;
    o.y = (bits & 2u) ? v.y * inv : v.y;
    o.z = (bits & 4u) ? v.z * inv : v.z;
    o.w = (bits & 8u) ? v.w * inv : v.w;
    ((float4*)out)[gid] = o;
}

extern "C" void kernel_launch(void* const* d_in, const int* in_sizes, int n_in,
                              void* d_out, int out_size) {
    const float* x = (const float*)d_in[0];
    float* out = (float*)d_out;
    k_init<<<1, 64>>>();
    k_mask<<<NPIX / 4 / 256, 256>>>(x);          // 1024 blocks
    k_stats<<<B_ * C_ * 4, 256>>>(x);            // 4096 blocks
    k_finalize<<<1, C_>>>(x);
    k_norm<<<NELEM / 4 / 256, 256>>>(x, out);    // 65536 blocks
}

// round 2
// speedup vs baseline: 1.0925x; 1.0925x over previous
#include <cuda_runtime.h>

#define B_    16
#define C_    64
#define WH    65536                 // 256*256
#define NPIX  (B_ * WH)             // 1,048,576 pixels
#define NELEM (B_ * C_ * WH)        // 67,108,864 elements
#define EPS_  0.001f

#define NBLK_MASK   1024            // 64 blocks per batch
#define NBLK_STATS  4096            // (b*64+c)*4 + chunk
#define NBLK_NORM   16384           // 1024 float4 per block

// ---- scratch (device globals; plain stores only, no init needed) ----
__device__ unsigned int g_mask[NPIX / 32];   // 1 bit per (b,w,h) pixel, 128 KB
__device__ int          g_cnt[NBLK_MASK];    // per-mask-block masked-pixel count
__device__ float4       g_Sp4[NBLK_STATS/4]; // per-stats-block partial sums
__device__ float4       g_Qp4[NBLK_STATS/4]; // per-stats-block partial sumsq
__device__ float        g_inv[C_];           // 1/sqrt(var+eps)
__device__ int          g_f[B_];             // pad_b > 0 flag

// ---- mask pass: m = (x[b,0,p]!=0 || x[b,1,p]!=0); bitmask + block counts ----
__global__ void __launch_bounds__(256) k_mask(const float* __restrict__ x) {
    int gid = blockIdx.x * 256 + threadIdx.x;      // 0 .. NPIX/4-1
    int pix = gid << 2;                            // global pixel index
    int b   = pix >> 16;
    int p   = pix & (WH - 1);
    float4 a = __ldg((const float4*)(x + (size_t)(b * C_    ) * WH + p));
    float4 c = __ldg((const float4*)(x + (size_t)(b * C_ + 1) * WH + p));
    unsigned nib = (((a.x != 0.0f) | (c.x != 0.0f)) ? 1u : 0u)
                 | (((a.y != 0.0f) | (c.y != 0.0f)) ? 2u : 0u)
                 | (((a.z != 0.0f) | (c.z != 0.0f)) ? 4u : 0u)
                 | (((a.w != 0.0f) | (c.w != 0.0f)) ? 8u : 0u);
    unsigned lane = threadIdx.x & 31u;
    // 8-lane groups assemble one 32-bit mask word (bit j <-> pixel wordbase+j)
    unsigned grpmask = 0xFFu << (lane & 24u);
    unsigned word = __reduce_or_sync(grpmask, nib << ((lane & 7u) * 4u));
    if ((lane & 7u) == 0u) g_mask[pix >> 5] = word;
    // per-block count (block never straddles a batch: 1024 pixels/block)
    int wsum = __reduce_add_sync(0xFFFFFFFFu, __popc(nib));
    __shared__ int sc[8];
    int w = threadIdx.x >> 5;
    if (lane == 0) sc[w] = wsum;
    __syncthreads();
    if (threadIdx.x == 0) {
        int s = 0;
        #pragma unroll
        for (int i = 0; i < 8; i++) s += sc[i];
        g_cnt[blockIdx.x] = s;
    }
}

// ---- stats pass: per-channel partial S = sum m*x, Q = sum m*x^2 (256 MB) ----
__global__ void __launch_bounds__(256) k_stats(const float* __restrict__ x) {
    int blk   = blockIdx.x;          // 0..4095
    int plane = blk >> 2;            // b*64 + c
    int chunk = blk & 3;
    int b = plane >> 6;
    const float4*       base  = (const float4*)(x + (size_t)plane * WH + chunk * 16384);
    const unsigned int* mbase = g_mask + (b << 11);
    int pbase = chunk * 16384;

    float s0 = 0.0f, s1 = 0.0f, q0 = 0.0f, q1 = 0.0f;
    #pragma unroll
    for (int k = 0; k < 16; k++) {
        int idx4 = k * 256 + threadIdx.x;
        float4 v = __ldg(base + idx4);
        int p = pbase + (idx4 << 2);
        unsigned mw   = __ldg(mbase + (p >> 5));     // L1 broadcast across 8 threads
        unsigned bits = (mw >> (p & 31)) & 0xFu;
        if (bits & 1u) { s0 += v.x; q0 = fmaf(v.x, v.x, q0); }
        if (bits & 2u) { s1 += v.y; q1 = fmaf(v.y, v.y, q1); }
        if (bits & 4u) { s0 += v.z; q0 = fmaf(v.z, v.z, q0); }
        if (bits & 8u) { s1 += v.w; q1 = fmaf(v.w, v.w, q1); }
    }
    float s = s0 + s1, q = q0 + q1;
    #pragma unroll
    for (int o = 16; o; o >>= 1) {
        s += __shfl_xor_sync(0xFFFFFFFFu, s, o);
        q += __shfl_xor_sync(0xFFFFFFFFu, q, o);
    }
    __shared__ float ss[8], sq[8];
    int w = threadIdx.x >> 5;
    if ((threadIdx.x & 31) == 0) { ss[w] = s; sq[w] = q; }
    __syncthreads();
    if (threadIdx.x == 0) {
        float S = 0.0f, Q = 0.0f;
        #pragma unroll
        for (int i = 0; i < 8; i++) { S += ss[i]; Q += sq[i]; }
        ((float*)g_Sp4)[blk] = S;    // plain store, no atomics
        ((float*)g_Qp4)[blk] = Q;
    }
}

// ---- finalize: 1 block x 1024 threads. counts -> nmax; partials+pad -> inv ----
__global__ void __launch_bounds__(1024) k_finalize(const float* __restrict__ x) {
    int t = threadIdx.x;             // 0..1023
    __shared__ float sh_x00[1024];   // x00[b*64+c]
    __shared__ int   sh_n[B_];
    __shared__ int   sh_nmax;

    // issue all long-latency loads up front (independent -> MLP)
    float x00 = __ldg(&x[(size_t)t << 16]);          // plane t, element 0
    int   cnt = g_cnt[t];
    int   c   = t >> 4, bb = t & 15;
    float4 s4 = g_Sp4[bb * C_ + c];                  // 4 chunks of (b=bb, c)
    float4 q4 = g_Qp4[bb * C_ + c];

    if (t < B_) sh_n[t] = 0;
    sh_x00[t] = x00;
    __syncthreads();

    // per-batch counts: each warp lies fully within one batch (64 blocks/batch)
    int wsum = __reduce_add_sync(0xFFFFFFFFu, cnt);
    if ((t & 31) == 0) atomicAdd(&sh_n[t >> 6], wsum);
    __syncthreads();
    if (t == 0) {
        int nmax = 0;
        #pragma unroll
        for (int b = 0; b < B_; b++) nmax = max(nmax, sh_n[b]);
        sh_nmax = nmax;
    }
    __syncthreads();
    int nmax = sh_nmax;
    if (t < B_) g_f[t] = (nmax - sh_n[t]) > 0 ? 1 : 0;

    // per-(b,c) contribution incl. padding term
    float S = s4.x + s4.y + s4.z + s4.w;
    float Q = q4.x + q4.y + q4.z + q4.w;
    float pad  = (float)(nmax - sh_n[bb]);
    float x00v = sh_x00[bb * C_ + c];
    S = fmaf(pad, x00v, S);
    Q = fmaf(pad * x00v, x00v, Q);
    // reduce the 16 batch-lanes of each channel (contiguous lanes, width 16)
    #pragma unroll
    for (int o = 8; o; o >>= 1) {
        S += __shfl_xor_sync(0xFFFFFFFFu, S, o, 16);
        Q += __shfl_xor_sync(0xFFFFFFFFu, Q, o, 16);
    }
    if ((t & 15) == 0) {
        float total = (float)(B_ * nmax);
        float mean  = S / total;
        float var   = Q / total - mean * mean;
        g_inv[c] = rsqrtf(var + EPS_);
    }
}

// ---- normalize: out = m ? x*inv : x, (0,0) pad override. Reverse order so
// the L2-resident tail of the stats pass is re-read before eviction. ----
__global__ void __launch_bounds__(256) k_norm(const float* __restrict__ x,
                                              float* __restrict__ out) {
    int blk = (NBLK_NORM - 1) - blockIdx.x;          // reverse address order
    size_t base4 = (size_t)blk * 1024;               // float4 index of block base
    int plane = (int)(base4 >> 14);                  // 16 blocks per plane
    int c = plane & (C_ - 1);
    int b = plane >> 6;
    int pbase = (int)((base4 << 2) & (WH - 1));

    float inv = __ldg(&g_inv[c]);
    float4 v[4];
    unsigned bits[4];
    #pragma unroll
    for (int k = 0; k < 4; k++) {                    // front-batched loads, MLP~8
        size_t i4 = base4 + k * 256 + threadIdx.x;
        v[k] = __ldcs((const float4*)x + i4);        // streaming: no reuse of x
        int p = pbase + (int)((k * 256 + threadIdx.x) << 2);
        unsigned mw = __ldg(&g_mask[(b << 11) + (p >> 5)]);
        bits[k] = (mw >> (p & 31)) & 0xFu;
        if (p == 0) bits[k] |= (unsigned)g_f[b];     // pad override at (0,0)
    }
    #pragma unroll
    for (int k = 0; k < 4; k++) {
        size_t i4 = base4 + k * 256 + threadIdx.x;
        float4 o;
        o.x = (bits[k] & 1u) ? v[k].x * inv : v[k].x;
        o.y = (bits[k] & 2u) ? v[k].y * inv : v[k].y;
        o.z = (bits[k] & 4u) ? v[k].z * inv : v[k].z;
        o.w = (bits[k] & 8u) ? v[k].w * inv : v[k].w;
        __stcs((float4*)out + i4, o);                // evict-first: protect x in L2
    }
}

extern "C" void kernel_launch(void* const* d_in, const int* in_sizes, int n_in,
                              void* d_out, int out_size) {
    const float* x = (const float*)d_in[0];
    float* out = (float*)d_out;
    k_mask    <<<NBLK_MASK, 256>>>(x);
    k_stats   <<<NBLK_STATS, 256>>>(x);
    k_finalize<<<1, 1024>>>(x);
    k_norm    <<<NBLK_NORM, 256>>>(x, out);
}

// round 3
// speedup vs baseline: 1.0957x; 1.0030x over previous
#include <cuda_runtime.h>

#define B_    16
#define C_    64
#define WH    65536                 // 256*256
#define NELEM (B_ * C_ * WH)        // 67,108,864 elements
#define EPS_  0.001f

#define NBLK_STATS  4096            // (b*64+c)*4 + chunk
#define NBLK_NORM   16384           // 1024 float4 per block

// ---- scratch (device globals; plain stores only, no init needed) ----
__device__ int    g_cnt[B_ * 4];             // per (batch, chunk) masked count
__device__ float4 g_Sp4[NBLK_STATS / 4];     // per-plane partial sums (4 chunks)
__device__ float4 g_Qp4[NBLK_STATS / 4];     // per-plane partial sumsq
__device__ float  g_inv[C_];                 // 1/sqrt(var+eps)

// ---- stats pass: S_c = sum x, Q_c = sum x^2 over EVERYTHING (zeros are
// exactly zero for unmasked pixels, so no mask needed). The 64 blocks that
// own channel-0 planes also read channel 1 and count masked pixels. ----
__global__ void __launch_bounds__(256) k_stats(const float* __restrict__ x) {
    int blk   = blockIdx.x;          // 0..4095
    int plane = blk >> 2;            // b*64 + c
    int chunk = blk & 3;
    int c = plane & (C_ - 1);
    const float4* base  = (const float4*)(x + (size_t)plane * WH + chunk * 16384);
    const float4* base1 = (const float4*)(x + (size_t)(plane + 1) * WH + chunk * 16384);
    bool docnt = (c == 0);

    float s0 = 0.0f, s1 = 0.0f, q0 = 0.0f, q1 = 0.0f;
    int cnt = 0;
    #pragma unroll
    for (int k = 0; k < 16; k++) {
        int i4 = k * 256 + threadIdx.x;
        float4 v = __ldg(base + i4);
        s0 += v.x; q0 = fmaf(v.x, v.x, q0);
        s1 += v.y; q1 = fmaf(v.y, v.y, q1);
        s0 += v.z; q0 = fmaf(v.z, v.z, q0);
        s1 += v.w; q1 = fmaf(v.w, v.w, q1);
        if (docnt) {                             // only 64/4096 blocks
            float4 w = __ldg(base1 + i4);
            cnt += (int)((v.x != 0.0f) | (w.x != 0.0f))
                 + (int)((v.y != 0.0f) | (w.y != 0.0f))
                 + (int)((v.z != 0.0f) | (w.z != 0.0f))
                 + (int)((v.w != 0.0f) | (w.w != 0.0f));
        }
    }
    float s = s0 + s1, q = q0 + q1;
    #pragma unroll
    for (int o = 16; o; o >>= 1) {
        s += __shfl_xor_sync(0xFFFFFFFFu, s, o);
        q += __shfl_xor_sync(0xFFFFFFFFu, q, o);
    }
    __shared__ float ss[8], sq[8];
    __shared__ int   sc[8];
    int w = threadIdx.x >> 5;
    if (docnt) cnt = __reduce_add_sync(0xFFFFFFFFu, cnt);
    if ((threadIdx.x & 31) == 0) { ss[w] = s; sq[w] = q; sc[w] = cnt; }
    __syncthreads();
    if (threadIdx.x == 0) {
        float S = 0.0f, Q = 0.0f;
        #pragma unroll
        for (int i = 0; i < 8; i++) { S += ss[i]; Q += sq[i]; }
        ((float*)g_Sp4)[blk] = S;                // plain stores, no atomics
        ((float*)g_Qp4)[blk] = Q;
        if (docnt) {
            int t = 0;
            #pragma unroll
            for (int i = 0; i < 8; i++) t += sc[i];
            g_cnt[(plane >> 6) * 4 + chunk] = t;
        }
    }
}

// ---- finalize: 1 block x 1024 threads. counts -> nmax; partials+pad -> inv ----
__global__ void __launch_bounds__(1024) k_finalize(const float* __restrict__ x) {
    int t = threadIdx.x;             // 0..1023
    __shared__ float sh_x00[1024];   // x00[b*64+c]
    __shared__ int   sh_n[B_];
    __shared__ int   sh_nmax;

    // issue all long-latency loads up front (independent -> MLP)
    float x00 = __ldg(&x[(size_t)t << 16]);          // plane t, element 0
    int   c   = t >> 4, bb = t & 15;
    float4 s4 = g_Sp4[bb * C_ + c];                  // 4 chunk-partials of (bb,c)
    float4 q4 = g_Qp4[bb * C_ + c];
    int cnt = (t < B_ * 4) ? g_cnt[t] : 0;

    sh_x00[t] = x00;
    if (t < B_ * 4) {                // reduce 4 chunks per batch (width-4 shfl)
        cnt += __shfl_xor_sync(0xFFFFFFFFu, cnt, 1, 4);
        cnt += __shfl_xor_sync(0xFFFFFFFFu, cnt, 2, 4);
        if ((t & 3) == 0) sh_n[t >> 2] = cnt;
    }
    __syncthreads();
    if (t == 0) {
        int nmax = 0;
        #pragma unroll
        for (int b = 0; b < B_; b++) nmax = max(nmax, sh_n[b]);
        sh_nmax = nmax;
    }
    __syncthreads();
    int nmax = sh_nmax;

    // per-(b,c) contribution incl. padding term
    float S = (s4.x + s4.y) + (s4.z + s4.w);
    float Q = (q4.x + q4.y) + (q4.z + q4.w);
    float pad  = (float)(nmax - sh_n[bb]);
    float x00v = sh_x00[bb * C_ + c];
    S = fmaf(pad, x00v, S);
    Q = fmaf(pad * x00v, x00v, Q);
    // reduce the 16 batch-lanes of each channel (contiguous lanes, width 16)
    #pragma unroll
    for (int o = 8; o; o >>= 1) {
        S += __shfl_xor_sync(0xFFFFFFFFu, S, o, 16);
        Q += __shfl_xor_sync(0xFFFFFFFFu, Q, o, 16);
    }
    if ((t & 15) == 0) {
        float total = (float)(B_ * nmax);
        float mean  = S / total;
        float var   = Q / total - mean * mean;
        g_inv[c] = rsqrtf(var + EPS_);
    }
}

// ---- normalize: out = x * inv[c], unconditionally (unmasked x are exact 0,
// so x*inv == x there; (0,0) pad override is also x00*inv). Reverse order to
// catch the L2-resident tail left by the stats pass. ----
__global__ void __launch_bounds__(256) k_norm(const float* __restrict__ x,
                                              float* __restrict__ out) {
    int blk = (NBLK_NORM - 1) - blockIdx.x;          // reverse address order
    size_t base4 = (size_t)blk * 1024;               // float4 index of block base
    int c = (int)(base4 >> 14) & (C_ - 1);           // block lies in one plane
    float inv = __ldg(&g_inv[c]);
    float4 v[4];
    #pragma unroll
    for (int k = 0; k < 4; k++)                      // front-batched loads
        v[k] = __ldcs((const float4*)x + base4 + k * 256 + threadIdx.x);
    #pragma unroll
    for (int k = 0; k < 4; k++) {
        float4 o;
        o.x = v[k].x * inv; o.y = v[k].y * inv;
        o.z = v[k].z * inv; o.w = v[k].w * inv;
        __stcs((float4*)out + base4 + k * 256 + threadIdx.x, o);
    }
}

extern "C" void kernel_launch(void* const* d_in, const int* in_sizes, int n_in,
                              void* d_out, int out_size) {
    const float* x = (const float*)d_in[0];
    float* out = (float*)d_out;
    k_stats   <<<NBLK_STATS, 256>>>(x);
    k_finalize<<<1, 1024>>>(x);
    k_norm    <<<NBLK_NORM, 256>>>(x, out);
}